// round 7
// baseline (speedup 1.0000x reference)
#include <cuda_runtime.h>
#include <math.h>
#include <stdint.h>

#define BB   32
#define SS   256
#define NN   50
#define DD   100
#define QDIM 768

#define NT   13      // n-tiles (104 cols: 100 W rows + w~ row + pad)
#define KT   13      // k-tiles (104 cols of A, 100 used)
#define AP   108     // A smem row stride (floats), conflict-free
#define LSTR 28      // per-lane B-frag stride (13 kt * 2 + 2 pad)
#define PAIRS_PER_BLK 4

__device__ float g_Qraw[BB * DD];
__device__ float g_cb[BB];
__device__ float g_Bf[BB * NT * 32 * LSTR];   // [b][nt][lane][28]
__device__ float g_WT[DD * DD];               // W^T: g_WT[d*100+e] = Vw[e*100+d]

// ---------------------------------------------------------------------------
__device__ __forceinline__ void mma_tf32(float c[4], const float* a,
                                         float b0, float b1)
{
    asm volatile(
        "mma.sync.aligned.m16n8k8.row.col.f32.tf32.tf32.f32 "
        "{%0,%1,%2,%3}, {%4,%5,%6,%7}, {%8,%9}, {%0,%1,%2,%3};\n"
        : "+f"(c[0]), "+f"(c[1]), "+f"(c[2]), "+f"(c[3])
        : "r"(__float_as_uint(a[0])), "r"(__float_as_uint(a[1])),
          "r"(__float_as_uint(a[2])), "r"(__float_as_uint(a[3])),
          "r"(__float_as_uint(b0)),  "r"(__float_as_uint(b1)));
}

// ---------------------------------------------------------------------------
// Kernel 0: W^T transpose (one small kernel, 40KB, stays L2/L1-hot)
// ---------------------------------------------------------------------------
__global__ __launch_bounds__(256) void wt_kernel(const float* __restrict__ Vw)
{
    for (int i = blockIdx.x * 256 + threadIdx.x; i < DD * DD; i += gridDim.x * 256) {
        int e = i / DD, d = i - e * DD;     // coalesced read of Vw
        g_WT[d * DD + e] = Vw[i];
    }
}

// ---------------------------------------------------------------------------
// Kernel 1a: g_Qraw[b][e] = q[b] . Qw[e] + Qb[e]   (grid 3200)
// ---------------------------------------------------------------------------
__global__ __launch_bounds__(128) void qproj_a(
    const float* __restrict__ q,
    const float* __restrict__ Qw,
    const float* __restrict__ Qb)
{
    int b = blockIdx.x / DD, e = blockIdx.x % DD;
    __shared__ float red[4];
    const float* qr = q + (size_t)b * QDIM;
    const float* wr = Qw + (size_t)e * QDIM;
    int tid = threadIdx.x, warp = tid >> 5, lane = tid & 31;

    float acc = 0.f;
    #pragma unroll 6
    for (int i = tid; i < QDIM; i += 128) acc += qr[i] * wr[i];
    #pragma unroll
    for (int o = 16; o; o >>= 1) acc += __shfl_xor_sync(0xffffffffu, acc, o);
    if (lane == 0) red[warp] = acc;
    __syncthreads();
    if (tid == 0)
        g_Qraw[b * DD + e] = red[0] + red[1] + red[2] + red[3] + Qb[e];
}

// ---------------------------------------------------------------------------
// Kernel 1b: per batch: normalize Q, w~ = Vw^T Qn, cb = Qn.Vb, build B frags
// ---------------------------------------------------------------------------
__global__ __launch_bounds__(128) void qproj_b(
    const float* __restrict__ Vw,
    const float* __restrict__ Vb)
{
    int b = blockIdx.x;
    __shared__ float sQ[DD];
    __shared__ float sWq[DD];
    __shared__ float red[4];

    int tid = threadIdx.x, warp = tid >> 5, lane = tid & 31;

    float qv = (tid < DD) ? g_Qraw[b * DD + tid] : 0.f;
    float ss = qv * qv;
    #pragma unroll
    for (int o = 16; o; o >>= 1) ss += __shfl_xor_sync(0xffffffffu, ss, o);
    if (lane == 0) red[warp] = ss;
    __syncthreads();
    if (tid == 0)
        red[0] = fmaxf(sqrtf(red[0] + red[1] + red[2] + red[3]), 1e-12f);
    __syncthreads();
    float inv = 1.0f / red[0];
    if (tid < DD) sQ[tid] = qv * inv;
    __syncthreads();

    if (tid < DD) {
        float a = 0.f;
        #pragma unroll 4
        for (int e = 0; e < DD; e++) a += sQ[e] * Vw[e * DD + tid];
        sWq[tid] = a;
    }
    if (warp == 0) {
        float a = 0.f;
        for (int e = lane; e < DD; e += 32) a += sQ[e] * Vb[e];
        #pragma unroll
        for (int o = 16; o; o >>= 1) a += __shfl_xor_sync(0xffffffffu, a, o);
        if (lane == 0) g_cb[b] = a;
    }
    __syncthreads();

    // build B fragments: rows 0..99 = W rows, row 100 = w~, else 0
    float* dst = g_Bf + (size_t)b * NT * 32 * LSTR;
    for (int i = tid; i < NT * 32 * (LSTR / 2); i += 128) {
        int slot = i % (LSTR / 2);
        int rem  = i / (LSTR / 2);
        int ln   = rem & 31;
        int nt   = rem >> 5;
        float v0 = 0.f, v1 = 0.f;
        if (slot < KT) {
            int g = ln >> 2, tg = ln & 3;
            int n  = nt * 8 + g;
            int d0 = slot * 8 + tg;
            int d1 = d0 + 4;
            if (n < 100) {
                if (d0 < 100) v0 = Vw[n * DD + d0];
                if (d1 < 100) v1 = Vw[n * DD + d1];
            } else if (n == 100) {
                if (d0 < 100) v0 = sWq[d0];
                if (d1 < 100) v1 = sWq[d1];
            }
        }
        dst[(nt * 32 + ln) * LSTR + slot * 2 + 0] = v0;
        dst[(nt * 32 + ln) * LSTR + slot * 2 + 1] = v1;
    }
}

// ---------------------------------------------------------------------------
// Kernel 2: per block = (b, 4 s-pairs). tf32 mma GEMM -> norms^2 + numerator
// only. Exact fp32 epilogue: t = att@v ; out = t W^T + sigma*b.
// ---------------------------------------------------------------------------
#define AK_FLOATS (112 * AP)                // 12096 (v tile; rows 100+ unused)
#define BF_FLOATS (NT * 32 * LSTR)          // 11648
#define F_AK    0
#define F_BF    (F_AK + AK_FLOATS)
#define F_VB    (F_BF + BF_FLOATS)          // 104
#define F_NORM  (F_VB + 104)                // 112
#define F_DOT   (F_NORM + 112)              // 112
#define F_ATT   (F_DOT + 112)               // 128
#define F_T     (F_ATT + 128)               // 256
#define F_MISC  (F_T + 256)                 // 8
#define SMEM_FLOATS_TOT (F_MISC + 8)

__global__ __launch_bounds__(256, 2) void attn_kernel(
    const float* __restrict__ v,
    const float* __restrict__ Vb,
    float* __restrict__ out)
{
    extern __shared__ float smf[];
    float* sAK   = smf + F_AK;      // v tile (never overwritten)
    float* sBf   = smf + F_BF;
    float* sVb   = smf + F_VB;
    float* snorm = smf + F_NORM;
    float* sdot  = smf + F_DOT;
    float* sAtt  = smf + F_ATT;
    float* st    = smf + F_T;
    float* sMisc = smf + F_MISC;

    int tid  = threadIdx.x;
    int warp = tid >> 5;
    int lane = tid & 31;

    int blk   = blockIdx.x;                  // 1024 blocks
    int b     = blk >> 5;                    // 32 blocks per batch
    int pair0 = (blk & 31) * PAIRS_PER_BLK;

    // ---- prologue: stage B frags (zeros baked in), bias, cb ----
    {
        const float4* gsrc = (const float4*)(g_Bf + (size_t)b * BF_FLOATS);
        float4* pb = (float4*)sBf;
        for (int i = tid; i < BF_FLOATS / 4; i += 256) pb[i] = gsrc[i];
    }
    if (tid < 104) sVb[tid] = (tid < 100) ? Vb[tid] : 0.f;
    if (tid == 128) sMisc[0] = g_cb[b];

    for (int p = 0; p < PAIRS_PER_BLK; p++) {
        __syncthreads();

        // ---- stage A = v tile (100 rows x 100 cols), float4 ----
        size_t vbase = (size_t)(b * 128 + pair0 + p) * 10000;
        for (int c = tid; c < 2500; c += 256) {
            int r = c / 25, dq = (c - r * 25) * 4;
            float4 val = *(const float4*)(v + vbase + r * DD + dq);
            *(float4*)(sAK + r * AP + dq) = val;
        }
        __syncthreads();

        // ---- GEMM: warps 0..6, 16-row m-tile each ----
        if (warp < 7) {
            int g = lane >> 2, tg = lane & 3;
            int mrow = warp * 16 + g;
            float cb = sMisc[0];

            float aR[KT][4];
            {
                const float* a0p = sAK + mrow * AP;
                const float* a1p = sAK + (mrow + 8) * AP;
                #pragma unroll
                for (int kt = 0; kt < KT; kt++) {
                    int k0 = kt * 8;
                    aR[kt][0] = a0p[k0 + tg];
                    aR[kt][1] = a1p[k0 + tg];
                    aR[kt][2] = a0p[k0 + tg + 4];
                    aR[kt][3] = a1p[k0 + tg + 4];
                }
            }
            float sq0 = 0.f, sq1 = 0.f;
            #pragma unroll 1
            for (int nt = 0; nt < NT; nt++) {
                const float4* bl = (const float4*)(sBf + (nt * 32 + lane) * LSTR);
                float c[4] = {0.f, 0.f, 0.f, 0.f};
                #pragma unroll
                for (int j = 0; j < 6; j++) {
                    float4 B4 = bl[j];
                    mma_tf32(c, aR[2 * j],     B4.x, B4.y);
                    mma_tf32(c, aR[2 * j + 1], B4.z, B4.w);
                }
                {
                    float4 B4 = bl[6];
                    mma_tf32(c, aR[12], B4.x, B4.y);
                }
                int col0 = nt * 8 + 2 * tg;
                if (col0 < 100) {
                    float bia = sVb[col0];
                    float k0 = c[0] + bia, k2 = c[2] + bia;
                    sq0 += k0 * k0;  sq1 += k2 * k2;
                }
                if (col0 + 1 < 100) {
                    float bia = sVb[col0 + 1];
                    float k1 = c[1] + bia, k3 = c[3] + bia;
                    sq0 += k1 * k1;  sq1 += k3 * k3;
                }
                if (nt == NT - 1 && tg == 2) {     // col 100 = numerator
                    if (mrow < 100)     sdot[mrow]     = c[0] + cb;
                    if (mrow + 8 < 100) sdot[mrow + 8] = c[2] + cb;
                }
            }
            sq0 += __shfl_xor_sync(0xffffffffu, sq0, 1);
            sq0 += __shfl_xor_sync(0xffffffffu, sq0, 2);
            sq1 += __shfl_xor_sync(0xffffffffu, sq1, 1);
            sq1 += __shfl_xor_sync(0xffffffffu, sq1, 2);
            if (tg == 0) {
                if (mrow < 100)     snorm[mrow]     = sq0;
                if (mrow + 8 < 100) snorm[mrow + 8] = sq1;
            }
        }
        __syncthreads();

        // ---- softmax per s (warps 0,1) ----
        if (warp < 2) {
            int s = warp;
            int rb = s * 50;
            float x0, x1;
            {
                int r = rb + lane;
                float l2 = sqrtf(snorm[r]);
                if (l2 == 0.0f) l2 = 1e-6f;
                float sc = sdot[r] / l2;
                sc = (sc == 0.0f) ? -10000.0f : sc;
                x0 = (sc > 0.0f) ? sc : 0.01f * sc;
            }
            x1 = -INFINITY;
            if (lane < NN - 32) {
                int r = rb + lane + 32;
                float l2 = sqrtf(snorm[r]);
                if (l2 == 0.0f) l2 = 1e-6f;
                float sc = sdot[r] / l2;
                sc = (sc == 0.0f) ? -10000.0f : sc;
                x1 = (sc > 0.0f) ? sc : 0.01f * sc;
            }
            float m = fmaxf(x0, x1);
            #pragma unroll
            for (int o = 16; o; o >>= 1) m = fmaxf(m, __shfl_xor_sync(0xffffffffu, m, o));
            float e0 = expf(x0 - m);
            float e1 = (lane < NN - 32) ? expf(x1 - m) : 0.0f;
            float sm = e0 + e1;
            #pragma unroll
            for (int o = 16; o; o >>= 1) sm += __shfl_xor_sync(0xffffffffu, sm, o);
            float inv = 1.0f / sm;
            float a0 = e0 * inv;
            if (a0 == (1.0f / 50.0f)) a0 = 0.0f;
            float a1 = 0.0f;
            if (lane < NN - 32) {
                a1 = e1 * inv;
                if (a1 == (1.0f / 50.0f)) a1 = 0.0f;
            }
            sAtt[rb + lane] = a0;
            if (lane < NN - 32) sAtt[rb + lane + 32] = a1;
            float sg = a0 + a1;
            #pragma unroll
            for (int o = 16; o; o >>= 1) sg += __shfl_xor_sync(0xffffffffu, sg, o);
            if (lane == 0) sMisc[1 + s] = sg;
        }
        __syncthreads();

        // ---- t[s][d] = sum_n att[s][n] * v[s*50+n][d]  (exact fp32) ----
        int s = tid >> 7;
        int e = tid & 127;
        if (e < 100) {
            float acc = 0.f;
            const float* ab = sAtt + s * 50;
            const float* kb = sAK + (s * 50) * AP + e;
            #pragma unroll 5
            for (int n = 0; n < NN; n++) acc += ab[n] * kb[n * AP];
            st[s * 128 + e] = acc;
        }
        __syncthreads();

        // ---- out[s][e] = sum_d t[s][d] * WT[d][e] + sigma_s * Vb[e] ----
        if (e < 100) {
            float acc = sMisc[1 + s] * sVb[e];
            const float* tp = st + s * 128;
            const float* wt = g_WT + e;
            #pragma unroll 4
            for (int dd = 0; dd < DD; dd++)
                acc += tp[dd] * wt[dd * DD];     // coalesced, L1-hot
            out[(size_t)(b * 128 + pair0 + p) * 200 + s * 100 + e] = acc;
        }
    }
}

// ---------------------------------------------------------------------------
extern "C" void kernel_launch(void* const* d_in, const int* in_sizes, int n_in,
                              void* d_out, int out_size)
{
    // metadata order: input_ent, q, k, v, Q_w, Q_b, V_w, V_b
    const float* q  = (const float*)d_in[1];
    const float* v  = (const float*)d_in[3];
    const float* Qw = (const float*)d_in[4];
    const float* Qb = (const float*)d_in[5];
    const float* Vw = (const float*)d_in[6];
    const float* Vb = (const float*)d_in[7];
    float* out = (float*)d_out;

    wt_kernel<<<10, 256>>>(Vw);
    qproj_a<<<BB * DD, 128>>>(q, Qw, Qb);
    qproj_b<<<BB, 128>>>(Vw, Vb);

    size_t smem_bytes = SMEM_FLOATS_TOT * sizeof(float);
    cudaFuncSetAttribute(attn_kernel, cudaFuncAttributeMaxDynamicSharedMemorySize,
                         (int)smem_bytes);
    attn_kernel<<<BB * SS / 2 / PAIRS_PER_BLK, 256, smem_bytes>>>(v, Vb, out);
}

// round 9
// speedup vs baseline: 2.0570x; 2.0570x over previous
#include <cuda_runtime.h>
#include <math.h>
#include <stdint.h>

#define BB   32
#define SS   256
#define NN   50
#define DD   100
#define QDIM 768

#define NT   13      // n-tiles (104 cols: 100 W rows + w~ row + pad)
#define KT   13      // k-tiles (104 cols of A, 100 used)
#define AP   108     // A smem row stride (floats), conflict-free
#define LSTR 28      // per-lane B-frag stride (13 kt * 2 + 2 pad)
#define PAIRS_PER_BLK 2

__device__ float g_Qraw[BB * DD];
__device__ float g_cb[BB];
__device__ float g_Bf[BB * NT * 32 * LSTR];   // [b][nt][lane][28]
__device__ float g_WT[DD * DD];               // W^T: g_WT[d*100+e] = Vw[e*100+d]
__device__ float g_T[BB * SS * DD];           // t vectors (att @ v), exact fp32
__device__ float g_sig[BB * SS];              // sum of final att per row

// ---------------------------------------------------------------------------
__device__ __forceinline__ void mma_tf32(float c[4], const float* a,
                                         float b0, float b1)
{
    asm volatile(
        "mma.sync.aligned.m16n8k8.row.col.f32.tf32.tf32.f32 "
        "{%0,%1,%2,%3}, {%4,%5,%6,%7}, {%8,%9}, {%0,%1,%2,%3};\n"
        : "+f"(c[0]), "+f"(c[1]), "+f"(c[2]), "+f"(c[3])
        : "r"(__float_as_uint(a[0])), "r"(__float_as_uint(a[1])),
          "r"(__float_as_uint(a[2])), "r"(__float_as_uint(a[3])),
          "r"(__float_as_uint(b0)),  "r"(__float_as_uint(b1)));
}

// ---------------------------------------------------------------------------
// Kernel 0: W^T transpose (40KB, one-time)
// ---------------------------------------------------------------------------
__global__ __launch_bounds__(256) void wt_kernel(const float* __restrict__ Vw)
{
    for (int i = blockIdx.x * 256 + threadIdx.x; i < DD * DD; i += gridDim.x * 256) {
        int e = i / DD, d = i - e * DD;
        g_WT[d * DD + e] = Vw[i];
    }
}

// ---------------------------------------------------------------------------
// Kernel 1a: g_Qraw[b][e] = q[b] . Qw[e] + Qb[e]   (grid 3200)
// ---------------------------------------------------------------------------
__global__ __launch_bounds__(128) void qproj_a(
    const float* __restrict__ q,
    const float* __restrict__ Qw,
    const float* __restrict__ Qb)
{
    int b = blockIdx.x / DD, e = blockIdx.x % DD;
    __shared__ float red[4];
    const float* qr = q + (size_t)b * QDIM;
    const float* wr = Qw + (size_t)e * QDIM;
    int tid = threadIdx.x, warp = tid >> 5, lane = tid & 31;

    float acc = 0.f;
    #pragma unroll 6
    for (int i = tid; i < QDIM; i += 128) acc += qr[i] * wr[i];
    #pragma unroll
    for (int o = 16; o; o >>= 1) acc += __shfl_xor_sync(0xffffffffu, acc, o);
    if (lane == 0) red[warp] = acc;
    __syncthreads();
    if (tid == 0)
        g_Qraw[b * DD + e] = red[0] + red[1] + red[2] + red[3] + Qb[e];
}

// ---------------------------------------------------------------------------
// Kernel 1b: per batch: normalize Q, w~ = Vw^T Qn, cb = Qn.Vb, build B frags
// ---------------------------------------------------------------------------
__global__ __launch_bounds__(128) void qproj_b(
    const float* __restrict__ Vw,
    const float* __restrict__ Vb)
{
    int b = blockIdx.x;
    __shared__ float sQ[DD];
    __shared__ float sWq[DD];
    __shared__ float red[4];

    int tid = threadIdx.x, warp = tid >> 5, lane = tid & 31;

    float qv = (tid < DD) ? g_Qraw[b * DD + tid] : 0.f;
    float ss = qv * qv;
    #pragma unroll
    for (int o = 16; o; o >>= 1) ss += __shfl_xor_sync(0xffffffffu, ss, o);
    if (lane == 0) red[warp] = ss;
    __syncthreads();
    if (tid == 0)
        red[0] = fmaxf(sqrtf(red[0] + red[1] + red[2] + red[3]), 1e-12f);
    __syncthreads();
    float inv = 1.0f / red[0];
    if (tid < DD) sQ[tid] = qv * inv;
    __syncthreads();

    if (tid < DD) {
        float a = 0.f;
        #pragma unroll 4
        for (int e = 0; e < DD; e++) a += sQ[e] * Vw[e * DD + tid];
        sWq[tid] = a;
    }
    if (warp == 0) {
        float a = 0.f;
        for (int e = lane; e < DD; e += 32) a += sQ[e] * Vb[e];
        #pragma unroll
        for (int o = 16; o; o >>= 1) a += __shfl_xor_sync(0xffffffffu, a, o);
        if (lane == 0) g_cb[b] = a;
    }
    __syncthreads();

    // B fragments: rows 0..99 = W rows, row 100 = w~, else 0
    float* dst = g_Bf + (size_t)b * NT * 32 * LSTR;
    for (int i = tid; i < NT * 32 * (LSTR / 2); i += 128) {
        int slot = i % (LSTR / 2);
        int rem  = i / (LSTR / 2);
        int ln   = rem & 31;
        int nt   = rem >> 5;
        float v0 = 0.f, v1 = 0.f;
        if (slot < KT) {
            int g = ln >> 2, tg = ln & 3;
            int n  = nt * 8 + g;
            int d0 = slot * 8 + tg;
            int d1 = d0 + 4;
            if (n < 100) {
                if (d0 < 100) v0 = Vw[n * DD + d0];
                if (d1 < 100) v1 = Vw[n * DD + d1];
            } else if (n == 100) {
                if (d0 < 100) v0 = sWq[d0];
                if (d1 < 100) v1 = sWq[d1];
            }
        }
        dst[(nt * 32 + ln) * LSTR + slot * 2 + 0] = v0;
        dst[(nt * 32 + ln) * LSTR + slot * 2 + 1] = v1;
    }
}

// ---------------------------------------------------------------------------
// Kernel 2: per block = (b, 2 s-pairs). tf32 mma GEMM (paired accumulators)
// -> norms^2 + numerator. softmax. t = att@v (exact). Writes t + sigma.
// ---------------------------------------------------------------------------
#define AK_FLOATS (112 * AP)                // 12096
#define BF_FLOATS (NT * 32 * LSTR)          // 11648
#define F_AK    0
#define F_BF    (F_AK + AK_FLOATS)
#define F_VB    (F_BF + BF_FLOATS)          // 104
#define F_NORM  (F_VB + 104)                // 112
#define F_DOT   (F_NORM + 112)              // 112
#define F_ATT   (F_DOT + 112)               // 128
#define F_MISC  (F_ATT + 128)               // 8
#define SMEM_FLOATS_TOT (F_MISC + 8)

__global__ __launch_bounds__(256, 2) void attn_kernel(
    const float* __restrict__ v,
    const float* __restrict__ Vb)
{
    extern __shared__ float smf[];
    float* sAK   = smf + F_AK;
    float* sBf   = smf + F_BF;
    float* sVb   = smf + F_VB;
    float* snorm = smf + F_NORM;
    float* sdot  = smf + F_DOT;
    float* sAtt  = smf + F_ATT;
    float* sMisc = smf + F_MISC;

    int tid  = threadIdx.x;
    int warp = tid >> 5;
    int lane = tid & 31;

    int blk   = blockIdx.x;                  // 2048 blocks
    int b     = blk >> 6;
    int pair0 = (blk & 63) * PAIRS_PER_BLK;

    // ---- prologue: zero A tile once (pads persist), stage B, bias, cb ----
    {
        float4 z = make_float4(0.f, 0.f, 0.f, 0.f);
        float4* pa = (float4*)sAK;
        for (int i = tid; i < AK_FLOATS / 4; i += 256) pa[i] = z;
        const float4* gsrc = (const float4*)(g_Bf + (size_t)b * BF_FLOATS);
        float4* pb = (float4*)sBf;
        for (int i = tid; i < BF_FLOATS / 4; i += 256) pb[i] = gsrc[i];
    }
    if (tid < 104) sVb[tid] = (tid < 100) ? Vb[tid] : 0.f;
    if (tid == 128) sMisc[0] = g_cb[b];

    for (int p = 0; p < PAIRS_PER_BLK; p++) {
        __syncthreads();

        int pp = b * 128 + pair0 + p;        // s-pair index
        size_t vbase = (size_t)pp * 10000;
        for (int c = tid; c < 2500; c += 256) {
            int r = c / 25, dq = (c - r * 25) * 4;
            float4 val = *(const float4*)(v + vbase + r * DD + dq);
            *(float4*)(sAK + r * AP + dq) = val;
        }
        __syncthreads();

        // ---- GEMM: warps 0..6, paired n-tiles, 2 independent acc chains ----
        if (warp < 7) {
            int g = lane >> 2, tg = lane & 3;
            int mrow = warp * 16 + g;
            float cb = sMisc[0];

            float aR[KT][4];
            {
                const float* a0p = sAK + mrow * AP;
                const float* a1p = sAK + (mrow + 8) * AP;
                #pragma unroll
                for (int kt = 0; kt < KT; kt++) {
                    int k0 = kt * 8;
                    aR[kt][0] = a0p[k0 + tg];
                    aR[kt][1] = a1p[k0 + tg];
                    aR[kt][2] = a0p[k0 + tg + 4];
                    aR[kt][3] = a1p[k0 + tg + 4];
                }
            }
            float sq0 = 0.f, sq1 = 0.f;

            #pragma unroll 1
            for (int np = 0; np < 6; np++) {        // nt = 2*np, 2*np+1
                int nt0 = 2 * np, nt1 = 2 * np + 1;
                const float4* bl0 = (const float4*)(sBf + (nt0 * 32 + lane) * LSTR);
                const float4* bl1 = (const float4*)(sBf + (nt1 * 32 + lane) * LSTR);
                float c0[4] = {0.f, 0.f, 0.f, 0.f};
                float c1[4] = {0.f, 0.f, 0.f, 0.f};
                #pragma unroll
                for (int j = 0; j < 6; j++) {
                    float4 B0 = bl0[j];
                    float4 B1 = bl1[j];
                    mma_tf32(c0, aR[2 * j],     B0.x, B0.y);
                    mma_tf32(c1, aR[2 * j],     B1.x, B1.y);
                    mma_tf32(c0, aR[2 * j + 1], B0.z, B0.w);
                    mma_tf32(c1, aR[2 * j + 1], B1.z, B1.w);
                }
                {
                    float4 B0 = bl0[6];
                    float4 B1 = bl1[6];
                    mma_tf32(c0, aR[12], B0.x, B0.y);
                    mma_tf32(c1, aR[12], B1.x, B1.y);
                }
                // squares (all cols < 100 for nt <= 11)
                int col0 = nt0 * 8 + 2 * tg;
                float bia0 = sVb[col0], bia1 = sVb[col0 + 1];
                float k0 = c0[0] + bia0, k2 = c0[2] + bia0;
                float k1 = c0[1] + bia1, k3 = c0[3] + bia1;
                sq0 += k0 * k0 + k1 * k1;
                sq1 += k2 * k2 + k3 * k3;
                int col1 = nt1 * 8 + 2 * tg;
                float bia2 = sVb[col1], bia3 = sVb[col1 + 1];
                float m0 = c1[0] + bia2, m2 = c1[2] + bia2;
                float m1 = c1[1] + bia3, m3 = c1[3] + bia3;
                sq0 += m0 * m0 + m1 * m1;
                sq1 += m2 * m2 + m3 * m3;
            }
            {   // nt = 12 (cols 96..103; numerator at col 100)
                const float4* bl = (const float4*)(sBf + (12 * 32 + lane) * LSTR);
                float c[4] = {0.f, 0.f, 0.f, 0.f};
                #pragma unroll
                for (int j = 0; j < 6; j++) {
                    float4 B4 = bl[j];
                    mma_tf32(c, aR[2 * j],     B4.x, B4.y);
                    mma_tf32(c, aR[2 * j + 1], B4.z, B4.w);
                }
                float4 B4 = bl[6];
                mma_tf32(c, aR[12], B4.x, B4.y);

                int col0 = 96 + 2 * tg;
                if (col0 < 100) {
                    float bia = sVb[col0];
                    float k0 = c[0] + bia, k2 = c[2] + bia;
                    sq0 += k0 * k0;  sq1 += k2 * k2;
                }
                if (col0 + 1 < 100) {
                    float bia = sVb[col0 + 1];
                    float k1 = c[1] + bia, k3 = c[3] + bia;
                    sq0 += k1 * k1;  sq1 += k3 * k3;
                }
                if (tg == 2) {                       // col 100 numerator
                    if (mrow < 100)     sdot[mrow]     = c[0] + cb;
                    if (mrow + 8 < 100) sdot[mrow + 8] = c[2] + cb;
                }
            }
            sq0 += __shfl_xor_sync(0xffffffffu, sq0, 1);
            sq0 += __shfl_xor_sync(0xffffffffu, sq0, 2);
            sq1 += __shfl_xor_sync(0xffffffffu, sq1, 1);
            sq1 += __shfl_xor_sync(0xffffffffu, sq1, 2);
            if (tg == 0) {
                if (mrow < 100)     snorm[mrow]     = sq0;
                if (mrow + 8 < 100) snorm[mrow + 8] = sq1;
            }
        }
        __syncthreads();

        // ---- softmax per s (warps 0,1) ----
        if (warp < 2) {
            int s = warp;
            int rb = s * 50;
            float x0, x1;
            {
                int r = rb + lane;
                float l2 = sqrtf(snorm[r]);
                if (l2 == 0.0f) l2 = 1e-6f;
                float sc = sdot[r] / l2;
                sc = (sc == 0.0f) ? -10000.0f : sc;
                x0 = (sc > 0.0f) ? sc : 0.01f * sc;
            }
            x1 = -INFINITY;
            if (lane < NN - 32) {
                int r = rb + lane + 32;
                float l2 = sqrtf(snorm[r]);
                if (l2 == 0.0f) l2 = 1e-6f;
                float sc = sdot[r] / l2;
                sc = (sc == 0.0f) ? -10000.0f : sc;
                x1 = (sc > 0.0f) ? sc : 0.01f * sc;
            }
            float m = fmaxf(x0, x1);
            #pragma unroll
            for (int o = 16; o; o >>= 1) m = fmaxf(m, __shfl_xor_sync(0xffffffffu, m, o));
            float e0 = expf(x0 - m);
            float e1 = (lane < NN - 32) ? expf(x1 - m) : 0.0f;
            float sm = e0 + e1;
            #pragma unroll
            for (int o = 16; o; o >>= 1) sm += __shfl_xor_sync(0xffffffffu, sm, o);
            float inv = 1.0f / sm;
            float a0 = e0 * inv;
            if (a0 == (1.0f / 50.0f)) a0 = 0.0f;
            float a1 = 0.0f;
            if (lane < NN - 32) {
                a1 = e1 * inv;
                if (a1 == (1.0f / 50.0f)) a1 = 0.0f;
            }
            sAtt[rb + lane] = a0;
            if (lane < NN - 32) sAtt[rb + lane + 32] = a1;
            float sg = a0 + a1;
            #pragma unroll
            for (int o = 16; o; o >>= 1) sg += __shfl_xor_sync(0xffffffffu, sg, o);
            if (lane == 0) g_sig[pp * 2 + s] = sg;
        }
        __syncthreads();

        // ---- t[s][e] = sum_n att[s][n] * v[s*50+n][e]  -> global (exact) ----
        int s = tid >> 7;
        int e = tid & 127;
        if (e < 100) {
            float acc = 0.f;
            const float* ab = sAtt + s * 50;
            const float* kb = sAK + (s * 50) * AP + e;
            #pragma unroll 5
            for (int n = 0; n < NN; n++) acc += ab[n] * kb[n * AP];
            g_T[(size_t)(pp * 2 + s) * DD + e] = acc;
        }
    }
}

// ---------------------------------------------------------------------------
// Kernel 3: out[r][e] = sum_d T[r][d] * WT[d][e] + sig[r] * Vb[e]
// grid = 8192/8 = 1024 blocks, 128 threads; W staged in smem (40KB)
// ---------------------------------------------------------------------------
#define OP_ROWS 8
__global__ __launch_bounds__(128) void out_proj(
    const float* __restrict__ Vb,
    float* __restrict__ out)
{
    __shared__ float sW[DD * DD];
    __shared__ float sT[OP_ROWS * DD];
    __shared__ float sS[OP_ROWS];

    int tid = threadIdx.x;
    int r0  = blockIdx.x * OP_ROWS;

    {   // stage WT (coalesced float4)
        const float4* src = (const float4*)g_WT;
        float4* dst = (float4*)sW;
        #pragma unroll
        for (int i = tid; i < DD * DD / 4; i += 128) dst[i] = src[i];
        const float4* tsrc = (const float4*)(g_T + (size_t)r0 * DD);
        float4* tdst = (float4*)sT;
        for (int i = tid; i < OP_ROWS * DD / 4; i += 128) tdst[i] = tsrc[i];
        if (tid < OP_ROWS) sS[tid] = g_sig[r0 + tid];
    }
    __syncthreads();

    int e = tid;
    if (e < DD) {
        float be = Vb[e];
        float acc[OP_ROWS];
        #pragma unroll
        for (int j = 0; j < OP_ROWS; j++) acc[j] = sS[j] * be;
        #pragma unroll 4
        for (int d = 0; d < DD; d++) {
            float w = sW[d * DD + e];
            #pragma unroll
            for (int j = 0; j < OP_ROWS; j++) acc[j] += sT[j * DD + d] * w;
        }
        #pragma unroll
        for (int j = 0; j < OP_ROWS; j++)
            out[(size_t)(r0 + j) * DD + e] = acc[j];
    }
}

// ---------------------------------------------------------------------------
extern "C" void kernel_launch(void* const* d_in, const int* in_sizes, int n_in,
                              void* d_out, int out_size)
{
    // metadata order: input_ent, q, k, v, Q_w, Q_b, V_w, V_b
    const float* q  = (const float*)d_in[1];
    const float* v  = (const float*)d_in[3];
    const float* Qw = (const float*)d_in[4];
    const float* Qb = (const float*)d_in[5];
    const float* Vw = (const float*)d_in[6];
    const float* Vb = (const float*)d_in[7];
    float* out = (float*)d_out;

    wt_kernel<<<10, 256>>>(Vw);
    qproj_a<<<BB * DD, 128>>>(q, Qw, Qb);
    qproj_b<<<BB, 128>>>(Vw, Vb);

    size_t smem_bytes = SMEM_FLOATS_TOT * sizeof(float);
    cudaFuncSetAttribute(attn_kernel, cudaFuncAttributeMaxDynamicSharedMemorySize,
                         (int)smem_bytes);
    attn_kernel<<<BB * SS / 2 / PAIRS_PER_BLK, 256, smem_bytes>>>(v, Vb);

    out_proj<<<BB * SS / OP_ROWS, 128>>>(Vb, out);
}

// round 10
// speedup vs baseline: 2.0759x; 1.0092x over previous
#include <cuda_runtime.h>
#include <math.h>
#include <stdint.h>

#define BB   32
#define SS   256
#define NN   50
#define DD   100
#define QDIM 768

#define NT   13      // n-tiles over 104 cols = 100 v-rows (2 s) + 4 pad
#define KT   13      // k-tiles over 104 (100 used)
#define AP   108     // v-tile row stride (floats), conflict-free
#define PAIRS_PER_BLK 2
#define AF_PER_B (7 * KT * 128)   // floats per batch in g_Af = 11648

__device__ float g_Qraw[BB * DD];
__device__ float g_cb[BB];
__device__ float g_Af[BB * AF_PER_B];   // A-frags of [W; w~] : [b][w][kt][lane][4]
__device__ float g_WT[DD * DD];         // W^T for out_proj
__device__ float g_T[BB * SS * DD];     // t = att @ v (exact fp32)
__device__ float g_sig[BB * SS];        // sum of final att per row

// ---------------------------------------------------------------------------
__device__ __forceinline__ void mma_tf32(float c[4], const float* a,
                                         float b0, float b1)
{
    asm volatile(
        "mma.sync.aligned.m16n8k8.row.col.f32.tf32.tf32.f32 "
        "{%0,%1,%2,%3}, {%4,%5,%6,%7}, {%8,%9}, {%0,%1,%2,%3};\n"
        : "+f"(c[0]), "+f"(c[1]), "+f"(c[2]), "+f"(c[3])
        : "r"(__float_as_uint(a[0])), "r"(__float_as_uint(a[1])),
          "r"(__float_as_uint(a[2])), "r"(__float_as_uint(a[3])),
          "r"(__float_as_uint(b0)),  "r"(__float_as_uint(b1)));
}

// ---------------------------------------------------------------------------
// Kernel 0: W^T (for out_proj)
// ---------------------------------------------------------------------------
__global__ __launch_bounds__(256) void wt_kernel(const float* __restrict__ Vw)
{
    for (int i = blockIdx.x * 256 + threadIdx.x; i < DD * DD; i += gridDim.x * 256) {
        int e = i / DD, d = i - e * DD;
        g_WT[d * DD + e] = Vw[i];
    }
}

// ---------------------------------------------------------------------------
// Kernel 1a: g_Qraw[b][e] = q[b] . Qw[e] + Qb[e]
// ---------------------------------------------------------------------------
__global__ __launch_bounds__(128) void qproj_a(
    const float* __restrict__ q,
    const float* __restrict__ Qw,
    const float* __restrict__ Qb)
{
    int b = blockIdx.x / DD, e = blockIdx.x % DD;
    __shared__ float red[4];
    const float* qr = q + (size_t)b * QDIM;
    const float* wr = Qw + (size_t)e * QDIM;
    int tid = threadIdx.x, warp = tid >> 5, lane = tid & 31;

    float acc = 0.f;
    #pragma unroll 6
    for (int i = tid; i < QDIM; i += 128) acc += qr[i] * wr[i];
    #pragma unroll
    for (int o = 16; o; o >>= 1) acc += __shfl_xor_sync(0xffffffffu, acc, o);
    if (lane == 0) red[warp] = acc;
    __syncthreads();
    if (tid == 0)
        g_Qraw[b * DD + e] = red[0] + red[1] + red[2] + red[3] + Qb[e];
}

// ---------------------------------------------------------------------------
// Kernel 1b: per batch: normalize Q, w~ = Vw^T Qn, cb = Qn.Vb, build A frags
// A GEMM rows: 0..99 = W rows, 100 = w~, 101..111 = 0; cols >= 100 -> 0
// Layout: g_Af[b][(w*KT+kt)*128 + lane*4 + j]  (coalesced float4 per lane)
// ---------------------------------------------------------------------------
__global__ __launch_bounds__(128) void qproj_b(
    const float* __restrict__ Vw,
    const float* __restrict__ Vb)
{
    int b = blockIdx.x;
    __shared__ float sQ[DD];
    __shared__ float sWq[DD];
    __shared__ float red[4];

    int tid = threadIdx.x, warp = tid >> 5, lane = tid & 31;

    float qv = (tid < DD) ? g_Qraw[b * DD + tid] : 0.f;
    float ss = qv * qv;
    #pragma unroll
    for (int o = 16; o; o >>= 1) ss += __shfl_xor_sync(0xffffffffu, ss, o);
    if (lane == 0) red[warp] = ss;
    __syncthreads();
    if (tid == 0)
        red[0] = fmaxf(sqrtf(red[0] + red[1] + red[2] + red[3]), 1e-12f);
    __syncthreads();
    float inv = 1.0f / red[0];
    if (tid < DD) sQ[tid] = qv * inv;
    __syncthreads();

    if (tid < DD) {
        float a = 0.f;
        #pragma unroll 4
        for (int e = 0; e < DD; e++) a += sQ[e] * Vw[e * DD + tid];
        sWq[tid] = a;
    }
    if (warp == 0) {
        float a = 0.f;
        for (int e = lane; e < DD; e += 32) a += sQ[e] * Vb[e];
        #pragma unroll
        for (int o = 16; o; o >>= 1) a += __shfl_xor_sync(0xffffffffu, a, o);
        if (lane == 0) g_cb[b] = a;
    }
    __syncthreads();

    float* dst = g_Af + (size_t)b * AF_PER_B;
    for (int i = tid; i < 7 * KT * 32; i += 128) {
        int ln = i & 31;
        int kt = (i >> 5) % KT;
        int w  = (i >> 5) / KT;
        int g = ln >> 2, tg = ln & 3;
        int m0 = w * 16 + g, m1 = m0 + 8;
        int k0 = kt * 8 + tg, k1 = k0 + 4;
        float a0 = 0.f, a1 = 0.f, a2 = 0.f, a3 = 0.f;
        if (m0 < 100) {
            if (k0 < 100) a0 = Vw[m0 * DD + k0];
            if (k1 < 100) a2 = Vw[m0 * DD + k1];
        } else if (m0 == 100) {
            if (k0 < 100) a0 = sWq[k0];
            if (k1 < 100) a2 = sWq[k1];
        }
        if (m1 < 100) {
            if (k0 < 100) a1 = Vw[m1 * DD + k0];
            if (k1 < 100) a3 = Vw[m1 * DD + k1];
        } else if (m1 == 100) {
            if (k0 < 100) a1 = sWq[k0];
            if (k1 < 100) a3 = sWq[k1];
        }
        float4 val = make_float4(a0, a1, a2, a3);
        *(float4*)(dst + (size_t)(w * KT + kt) * 128 + ln * 4) = val;
    }
}

// ---------------------------------------------------------------------------
// Kernel 2: W-in-registers tf32 GEMM. D[e][r] = K[r][e]; col sums of squares
// via butterfly + per-warp partials; row 100 = score numerator.
// ---------------------------------------------------------------------------
#define F_V     0
#define F_PART  (F_V + 104 * AP)            // 7 * 112 = 784
#define F_DOT   (F_PART + 7 * 112)          // 112
#define F_ATT   (F_DOT + 112)               // 128
#define SMEM_FLOATS_TOT (F_ATT + 128)

__global__ __launch_bounds__(256, 3) void attn_kernel(
    const float* __restrict__ v,
    const float* __restrict__ Vb)
{
    extern __shared__ float smf[];
    float* sV    = smf + F_V;
    float* sPart = smf + F_PART;
    float* sdot  = smf + F_DOT;
    float* sAtt  = smf + F_ATT;

    int tid  = threadIdx.x;
    int warp = tid >> 5;
    int lane = tid & 31;
    int g    = lane >> 2;
    int tg   = lane & 3;

    int blk   = blockIdx.x;                  // 2048 blocks
    int b     = blk >> 6;                    // 64 blocks per batch
    int pair0 = (blk & 63) * PAIRS_PER_BLK;

    // ---- per-block constants ----
    float cb = g_cb[b];

    // A fragments (W + w~) into registers, coalesced
    float4 aW[KT];
    float bias0 = 0.f, bias1 = 0.f, mval0 = 0.f, mval1 = 0.f;
    if (warp < 7) {
        const float4* src = (const float4*)(g_Af + (size_t)b * AF_PER_B
                                            + (size_t)warp * KT * 128);
        #pragma unroll
        for (int kt = 0; kt < KT; kt++) aW[kt] = src[kt * 32 + lane];
        int m0 = warp * 16 + g, m1 = m0 + 8;
        if (m0 < 100) { bias0 = Vb[m0]; mval0 = 1.f; }
        if (m1 < 100) { bias1 = Vb[m1]; mval1 = 1.f; }
    }

    // ---- one-time pad zeroing of the v tile ----
    // cols 100..107 of rows 0..99
    if (tid < 200) {
        int r = tid >> 1, h = tid & 1;
        *(float4*)(sV + r * AP + 100 + 4 * h) = make_float4(0.f, 0.f, 0.f, 0.f);
    }
    // rows 100..103 entirely
    for (int i = tid; i < 4 * AP; i += 256) sV[100 * AP + i] = 0.f;

    for (int p = 0; p < PAIRS_PER_BLK; p++) {
        __syncthreads();

        int pp = b * 128 + pair0 + p;
        size_t vbase = (size_t)pp * 10000;
        for (int c = tid; c < 2500; c += 256) {
            int r = c / 25, dq = (c - r * 25) * 4;
            float4 val = *(const float4*)(v + vbase + r * DD + dq);
            *(float4*)(sV + r * AP + dq) = val;
        }
        __syncthreads();

        // ---- GEMM: warps 0..6; per nt: 13 mma, B = v scalar LDS ----
        if (warp < 7) {
            #pragma unroll 1
            for (int nt = 0; nt < NT; nt++) {
                const float* br = sV + (nt * 8 + g) * AP + tg;
                float c[4] = {0.f, 0.f, 0.f, 0.f};
                #pragma unroll
                for (int kt = 0; kt < KT; kt++)
                    mma_tf32(c, (const float*)&aW[kt], br[kt * 8], br[kt * 8 + 4]);

                // squares per column (rows = e), masked for invalid rows
                float k0 = c[0] + bias0, k1 = c[1] + bias0;
                float k2 = c[2] + bias1, k3 = c[3] + bias1;
                float s0 = mval0 * k0 * k0 + mval1 * k2 * k2;   // col nt*8+2tg
                float s1 = mval0 * k1 * k1 + mval1 * k3 * k3;   // col nt*8+2tg+1
                #pragma unroll
                for (int o = 4; o <= 16; o <<= 1) {
                    s0 += __shfl_xor_sync(0xffffffffu, s0, o);
                    s1 += __shfl_xor_sync(0xffffffffu, s1, o);
                }
                if (g == 0) {
                    sPart[warp * 112 + nt * 8 + 2 * tg]     = s0;
                    sPart[warp * 112 + nt * 8 + 2 * tg + 1] = s1;
                }
                // numerator: GEMM row 100 lives in warp 6, g == 4 (c[0], c[1])
                if (warp == 6 && g == 4) {
                    sdot[nt * 8 + 2 * tg]     = c[0] + cb;
                    sdot[nt * 8 + 2 * tg + 1] = c[1] + cb;
                }
            }
        }
        __syncthreads();

        // ---- softmax per s (warps 0,1); folds the 7-way partial sum ----
        if (warp < 2) {
            int s = warp;
            int rb = s * 50;
            float x0, x1;
            {
                int r = rb + lane;
                float nrm = 0.f;
                #pragma unroll
                for (int w = 0; w < 7; w++) nrm += sPart[w * 112 + r];
                float l2 = sqrtf(nrm);
                if (l2 == 0.0f) l2 = 1e-6f;
                float sc = sdot[r] / l2;
                sc = (sc == 0.0f) ? -10000.0f : sc;
                x0 = (sc > 0.0f) ? sc : 0.01f * sc;
            }
            x1 = -INFINITY;
            if (lane < NN - 32) {
                int r = rb + lane + 32;
                float nrm = 0.f;
                #pragma unroll
                for (int w = 0; w < 7; w++) nrm += sPart[w * 112 + r];
                float l2 = sqrtf(nrm);
                if (l2 == 0.0f) l2 = 1e-6f;
                float sc = sdot[r] / l2;
                sc = (sc == 0.0f) ? -10000.0f : sc;
                x1 = (sc > 0.0f) ? sc : 0.01f * sc;
            }
            float m = fmaxf(x0, x1);
            #pragma unroll
            for (int o = 16; o; o >>= 1) m = fmaxf(m, __shfl_xor_sync(0xffffffffu, m, o));
            float e0 = expf(x0 - m);
            float e1 = (lane < NN - 32) ? expf(x1 - m) : 0.0f;
            float sm = e0 + e1;
            #pragma unroll
            for (int o = 16; o; o >>= 1) sm += __shfl_xor_sync(0xffffffffu, sm, o);
            float inv = 1.0f / sm;
            float a0 = e0 * inv;
            if (a0 == (1.0f / 50.0f)) a0 = 0.0f;
            float a1 = 0.0f;
            if (lane < NN - 32) {
                a1 = e1 * inv;
                if (a1 == (1.0f / 50.0f)) a1 = 0.0f;
            }
            sAtt[rb + lane] = a0;
            if (lane < NN - 32) sAtt[rb + lane + 32] = a1;
            float sg = a0 + a1;
            #pragma unroll
            for (int o = 16; o; o >>= 1) sg += __shfl_xor_sync(0xffffffffu, sg, o);
            if (lane == 0) g_sig[pp * 2 + s] = sg;
        }
        __syncthreads();

        // ---- t[s][e] = sum_n att[s][n] * v[s*50+n][e]  (exact fp32) ----
        int s = tid >> 7;
        int e = tid & 127;
        if (e < 100) {
            float acc = 0.f;
            const float* ab = sAtt + s * 50;
            const float* kb = sV + (s * 50) * AP + e;
            #pragma unroll 5
            for (int n = 0; n < NN; n++) acc += ab[n] * kb[n * AP];
            g_T[(size_t)(pp * 2 + s) * DD + e] = acc;
        }
    }
}

// ---------------------------------------------------------------------------
// Kernel 3: out[r][e] = sum_d T[r][d] * WT[d][e] + sig[r] * Vb[e]
// ---------------------------------------------------------------------------
#define OP_ROWS 16
__global__ __launch_bounds__(128) void out_proj(
    const float* __restrict__ Vb,
    float* __restrict__ out)
{
    __shared__ float sW[DD * DD];
    __shared__ float sT[OP_ROWS * DD];
    __shared__ float sS[OP_ROWS];

    int tid = threadIdx.x;
    int r0  = blockIdx.x * OP_ROWS;

    {
        const float4* src = (const float4*)g_WT;
        float4* dst = (float4*)sW;
        #pragma unroll
        for (int i = tid; i < DD * DD / 4; i += 128) dst[i] = src[i];
        const float4* tsrc = (const float4*)(g_T + (size_t)r0 * DD);
        float4* tdst = (float4*)sT;
        for (int i = tid; i < OP_ROWS * DD / 4; i += 128) tdst[i] = tsrc[i];
        if (tid < OP_ROWS) sS[tid] = g_sig[r0 + tid];
    }
    __syncthreads();

    int e = tid;
    if (e < DD) {
        float be = Vb[e];
        float acc[OP_ROWS];
        #pragma unroll
        for (int j = 0; j < OP_ROWS; j++) acc[j] = sS[j] * be;
        #pragma unroll 2
        for (int d = 0; d < DD; d++) {
            float w = sW[d * DD + e];
            #pragma unroll
            for (int j = 0; j < OP_ROWS; j++) acc[j] += sT[j * DD + d] * w;
        }
        #pragma unroll
        for (int j = 0; j < OP_ROWS; j++)
            out[(size_t)(r0 + j) * DD + e] = acc[j];
    }
}

// ---------------------------------------------------------------------------
extern "C" void kernel_launch(void* const* d_in, const int* in_sizes, int n_in,
                              void* d_out, int out_size)
{
    // metadata order: input_ent, q, k, v, Q_w, Q_b, V_w, V_b
    const float* q  = (const float*)d_in[1];
    const float* v  = (const float*)d_in[3];
    const float* Qw = (const float*)d_in[4];
    const float* Qb = (const float*)d_in[5];
    const float* Vw = (const float*)d_in[6];
    const float* Vb = (const float*)d_in[7];
    float* out = (float*)d_out;

    wt_kernel<<<10, 256>>>(Vw);
    qproj_a<<<BB * DD, 128>>>(q, Qw, Qb);
    qproj_b<<<BB, 128>>>(Vw, Vb);

    size_t smem_bytes = SMEM_FLOATS_TOT * sizeof(float);
    cudaFuncSetAttribute(attn_kernel, cudaFuncAttributeMaxDynamicSharedMemorySize,
                         (int)smem_bytes);
    attn_kernel<<<BB * SS / 2 / PAIRS_PER_BLK, 256, smem_bytes>>>(v, Vb);

    out_proj<<<BB * SS / OP_ROWS, 128>>>(Vb, out);
}